// round 3
// baseline (speedup 1.0000x reference)
#include <cuda_runtime.h>

#define HBV   20
#define DV    40
#define WPAD  28          // padded weight row: 112B
#define WARPS 4
#define EPW   8           // elements per warp
#define FULLM 0xffffffffu

__global__ __launch_bounds__(128)
void ende_kernel(const float* __restrict__ x,
                 const float* __restrict__ w1g,
                 const float* __restrict__ w2g,
                 const float* __restrict__ w3g,
                 const float* __restrict__ w4g,
                 float* __restrict__ out_vec,
                 float* __restrict__ out_jt)
{
    __shared__ __align__(16) float sw1[HBV * WPAD];
    __shared__ __align__(16) float sw2[HBV * WPAD];
    __shared__ __align__(16) float sw3[HBV * WPAD];
    __shared__ __align__(16) float sw4[HBV * WPAD];
    __shared__ __align__(16) float p1s[WARPS][HBV];
    __shared__ __align__(16) float s2s[WARPS][HBV];
    __shared__ __align__(16) float jjb[WARPS][HBV * HBV];

    const int tid = threadIdx.x;

    // Stage weights into padded smem (once per block)
    for (int idx = tid; idx < HBV * HBV; idx += 128) {
        int r = idx / HBV, c = idx % HBV;
        sw1[r * WPAD + c] = w1g[idx];
        sw2[r * WPAD + c] = w2g[idx];
        sw3[r * WPAD + c] = w3g[idx];
        sw4[r * WPAD + c] = w4g[idx];
    }
    __syncthreads();

    const int w = tid >> 5;
    const int l = tid & 31;

    // Per-lane register cache of W1/W2 COLUMN l (amortized over EPW elements)
    float W1c[HBV], W2c[HBV];
    {
        const int cc = (l < HBV) ? l : 0;
        #pragma unroll
        for (int k = 0; k < HBV; k++) {
            W1c[k] = sw1[k * WPAD + cc];
            W2c[k] = sw2[k * WPAD + cc];
        }
    }

    const long long wg = (long long)blockIdx.x * WARPS + w;

    for (int it = 0; it < EPW; ++it) {
        const long long b = wg * EPW + it;
        const float* xr = x + b * DV;

        float p1_own = 0.f, p2_own = 0.f;
        if (l < HBV) {
            p1_own = xr[l];
            p2_own = xr[HBV + l];
            p1s[w][l] = p1_own;
        }
        __syncwarp();

        // ---- Stage A: f1 = tanh(W1 p1), f2 = tanh(W2 p1) ----
        float b12x = 0.f, b12y = 0.f, e2_own = 0.f, s2_own = 0.f;
        if (l < HBV) {
            float a1 = 0.f, a2 = 0.f;
            const float4* r1 = (const float4*)(sw1 + l * WPAD);
            const float4* r2 = (const float4*)(sw2 + l * WPAD);
            const float4* pv = (const float4*)(p1s[w]);
            #pragma unroll
            for (int g = 0; g < 5; g++) {
                float4 A = r1[g], Bv = r2[g], P = pv[g];
                a1 = fmaf(A.x,  P.x, a1); a1 = fmaf(A.y,  P.y, a1);
                a1 = fmaf(A.z,  P.z, a1); a1 = fmaf(A.w,  P.w, a1);
                a2 = fmaf(Bv.x, P.x, a2); a2 = fmaf(Bv.y, P.y, a2);
                a2 = fmaf(Bv.z, P.z, a2); a2 = fmaf(Bv.w, P.w, a2);
            }
            float f1 = tanhf(a1);
            float f2 = tanhf(a2);
            e2_own = expf(f2);
            float p2e = p2_own * e2_own;
            s2_own = p2e + f1;
            s2s[w][l] = s2_own;
            b12x = 1.f - f1 * f1;
            b12y = p2e * (1.f - f2 * f2);
        }
        __syncwarp();

        // ---- Stage B: f3 = tanh(W3 s2), f4 = tanh(W4 s2) ----
        float e4_own = 0.f, a34x = 0.f, a34y = 0.f, t1 = 0.f;
        if (l < HBV) {
            float a3 = 0.f, a4 = 0.f;
            const float4* r3 = (const float4*)(sw3 + l * WPAD);
            const float4* r4 = (const float4*)(sw4 + l * WPAD);
            const float4* sv = (const float4*)(s2s[w]);
            #pragma unroll
            for (int g = 0; g < 5; g++) {
                float4 A = r3[g], Bv = r4[g], S = sv[g];
                a3 = fmaf(A.x,  S.x, a3); a3 = fmaf(A.y,  S.y, a3);
                a3 = fmaf(A.z,  S.z, a3); a3 = fmaf(A.w,  S.w, a3);
                a4 = fmaf(Bv.x, S.x, a4); a4 = fmaf(Bv.y, S.y, a4);
                a4 = fmaf(Bv.z, S.z, a4); a4 = fmaf(Bv.w, S.w, a4);
            }
            float f3 = tanhf(a3);
            float f4 = tanhf(a4);
            e4_own = expf(f4);
            float s1e = p1_own * e4_own;
            t1 = s1e + f3;
            a34x = 1.f - f3 * f3;
            a34y = s1e * (1.f - f4 * f4);
        }

        float* jt = out_jt + b * (DV * DV);

        // ---- out vector: one full-row float2 store (lanes 0..19 cover 160B) ----
        {
            float o0 = __shfl_sync(FULLM, t1,     (2 * l)      & 31);
            float o1 = __shfl_sync(FULLM, t1,     (2 * l + 1)  & 31);
            float o2 = __shfl_sync(FULLM, s2_own, (2 * l - 20) & 31);
            float o3 = __shfl_sync(FULLM, s2_own, (2 * l - 19) & 31);
            float2 st = (l < 10) ? make_float2(o0, o1) : make_float2(o2, o3);
            if (l < HBV) *(float2*)(out_vec + b * DV + 2 * l) = st;
        }

        // ---- J21 (registers only) + bottom rows [J21 | diag(e2)] merged store ----
        float J21r[HBV];
        #pragma unroll
        for (int k = 0; k < HBV; k++) {
            float b1  = __shfl_sync(FULLM, b12x, k);
            float b2  = __shfl_sync(FULLM, b12y, k);
            float v   = fmaf(b1, W1c[k], b2 * W2c[k]);
            J21r[k] = v;
            float e2k = __shfl_sync(FULLM, e2_own, k);
            float v0  = __shfl_sync(FULLM, v, (2 * l)     & 31);
            float v1  = __shfl_sync(FULLM, v, (2 * l + 1) & 31);
            float2 st;
            if (l < 10) {
                st = make_float2(v0, v1);
            } else {
                int c0 = 2 * l - 20;
                st = make_float2(c0 == k ? e2k : 0.f, (c0 + 1) == k ? e2k : 0.f);
            }
            if (l < HBV) *(float2*)(jt + (HBV + k) * DV + 2 * l) = st;
        }

        // ---- JJ12: regs (jjc) + smem (jjb) for the TL broadcast matmul ----
        float jjc[HBV];
        #pragma unroll
        for (int i = 0; i < HBV; i++) {
            float a3 = __shfl_sync(FULLM, a34x, i);
            float a4 = __shfl_sync(FULLM, a34y, i);
            float v = 0.f;
            if (l < HBV) {
                v = fmaf(a3, sw3[i * WPAD + l], a4 * sw4[i * WPAD + l]);
                jjb[w][i * HBV + l] = v;
            }
            jjc[i] = v;
        }
        __syncwarp();

        // ---- TL = diag(e4) + JJ12 @ J21; top rows [TL | JJ12*e2] merged store ----
        #pragma unroll
        for (int i = 0; i < HBV; i++) {
            const float4* rv = (const float4*)(jjb[w] + i * HBV);
            float m = 0.f;
            #pragma unroll
            for (int g = 0; g < 5; g++) {
                float4 c = rv[g];
                m = fmaf(c.x, J21r[4 * g + 0], m);
                m = fmaf(c.y, J21r[4 * g + 1], m);
                m = fmaf(c.z, J21r[4 * g + 2], m);
                m = fmaf(c.w, J21r[4 * g + 3], m);
            }
            if (i == l) m += e4_own;
            float gv = jjc[i] * e2_own;
            float m0 = __shfl_sync(FULLM, m,  (2 * l)      & 31);
            float m1 = __shfl_sync(FULLM, m,  (2 * l + 1)  & 31);
            float g0 = __shfl_sync(FULLM, gv, (2 * l - 20) & 31);
            float g1 = __shfl_sync(FULLM, gv, (2 * l - 19) & 31);
            float2 st = (l < 10) ? make_float2(m0, m1) : make_float2(g0, g1);
            if (l < HBV) *(float2*)(jt + i * DV + 2 * l) = st;
        }
        __syncwarp();   // protect p1s/s2s/jjb reuse next iteration
    }
}

extern "C" void kernel_launch(void* const* d_in, const int* in_sizes, int n_in,
                              void* d_out, int out_size) {
    const float* x  = (const float*)d_in[0];
    const float* w1 = (const float*)d_in[1];
    const float* w2 = (const float*)d_in[2];
    const float* w3 = (const float*)d_in[3];
    const float* w4 = (const float*)d_in[4];

    const int B = in_sizes[0] / DV;            // 65536
    float* out_vec = (float*)d_out;            // tuple element 0: (B,1,40)
    float* out_jt  = out_vec + (size_t)B * DV; // tuple element 1: (B,40,40)

    const int blocks = B / (WARPS * EPW);      // 2048
    ende_kernel<<<blocks, 128>>>(x, w1, w2, w3, w4, out_vec, out_jt);
}

// round 4
// speedup vs baseline: 1.4399x; 1.4399x over previous
#include <cuda_runtime.h>

#define HBV   20
#define DV    40
#define WPAD  28          // padded weight row: 112B, float4-aligned
#define WARPS 4
#define EPW   4           // elements per warp (amortizes W1/W2 column regs)

__global__ __launch_bounds__(128)
void ende_kernel(const float* __restrict__ x,
                 const float* __restrict__ w1g,
                 const float* __restrict__ w2g,
                 const float* __restrict__ w3g,
                 const float* __restrict__ w4g,
                 float* __restrict__ out_vec,
                 float* __restrict__ out_jt)
{
    __shared__ __align__(16) float sw1[HBV * WPAD];
    __shared__ __align__(16) float sw2[HBV * WPAD];
    __shared__ __align__(16) float sw3[HBV * WPAD];
    __shared__ __align__(16) float sw4[HBV * WPAD];
    __shared__ __align__(16) float p1s[WARPS][HBV];
    __shared__ __align__(16) float s2s[WARPS][HBV];
    __shared__ __align__(16) float4 cfs[WARPS][HBV];   // (b12x,b12y,a34x,a34y)
    __shared__ __align__(16) float jjb[WARPS][HBV * HBV];

    const int tid = threadIdx.x;

    // Stage weights into padded smem (once per block)
    for (int idx = tid; idx < HBV * HBV; idx += 128) {
        int r = idx / HBV, c = idx % HBV;
        sw1[r * WPAD + c] = w1g[idx];
        sw2[r * WPAD + c] = w2g[idx];
        sw3[r * WPAD + c] = w3g[idx];
        sw4[r * WPAD + c] = w4g[idx];
    }
    __syncthreads();

    const int w = tid >> 5;
    const int l = tid & 31;

    // Register cache of W1/W2 COLUMN l (conflict-free loads, amortized over EPW)
    float W1c[HBV], W2c[HBV];
    {
        const int cc = (l < HBV) ? l : 0;
        #pragma unroll
        for (int k = 0; k < HBV; k++) {
            W1c[k] = sw1[k * WPAD + cc];
            W2c[k] = sw2[k * WPAD + cc];
        }
    }

    const long long wg = (long long)blockIdx.x * WARPS + w;

    #pragma unroll 1
    for (int it = 0; it < EPW; ++it) {
        const long long b = wg * EPW + it;
        const float* xr = x + b * DV;

        float p1_own = 0.f, p2_own = 0.f;
        if (l < HBV) {
            p1_own = xr[l];
            p2_own = xr[HBV + l];
            p1s[w][l] = p1_own;
        }
        __syncwarp();

        // ---- Stage A: f1 = tanh(W1 p1), f2 = tanh(W2 p1) ----
        float e2_own = 0.f, s2_own = 0.f;
        if (l < HBV) {
            float a1 = 0.f, a2 = 0.f;
            const float4* r1 = (const float4*)(sw1 + l * WPAD);
            const float4* r2 = (const float4*)(sw2 + l * WPAD);
            const float4* pv = (const float4*)(p1s[w]);
            #pragma unroll
            for (int g = 0; g < 5; g++) {
                float4 A = r1[g], Bv = r2[g], P = pv[g];
                a1 = fmaf(A.x,  P.x, a1); a1 = fmaf(A.y,  P.y, a1);
                a1 = fmaf(A.z,  P.z, a1); a1 = fmaf(A.w,  P.w, a1);
                a2 = fmaf(Bv.x, P.x, a2); a2 = fmaf(Bv.y, P.y, a2);
                a2 = fmaf(Bv.z, P.z, a2); a2 = fmaf(Bv.w, P.w, a2);
            }
            float f1 = tanhf(a1);
            float f2 = tanhf(a2);
            e2_own = expf(f2);
            float p2e = p2_own * e2_own;
            s2_own = p2e + f1;
            s2s[w][l] = s2_own;
            float2* c01 = (float2*)&cfs[w][l];
            *c01 = make_float2(1.f - f1 * f1, p2e * (1.f - f2 * f2));
        }
        __syncwarp();

        // ---- Stage B: f3 = tanh(W3 s2), f4 = tanh(W4 s2) + out vector ----
        float e4_own = 0.f;
        if (l < HBV) {
            float a3 = 0.f, a4 = 0.f;
            const float4* r3 = (const float4*)(sw3 + l * WPAD);
            const float4* r4 = (const float4*)(sw4 + l * WPAD);
            const float4* sv = (const float4*)(s2s[w]);
            #pragma unroll
            for (int g = 0; g < 5; g++) {
                float4 A = r3[g], Bv = r4[g], S = sv[g];
                a3 = fmaf(A.x,  S.x, a3); a3 = fmaf(A.y,  S.y, a3);
                a3 = fmaf(A.z,  S.z, a3); a3 = fmaf(A.w,  S.w, a3);
                a4 = fmaf(Bv.x, S.x, a4); a4 = fmaf(Bv.y, S.y, a4);
                a4 = fmaf(Bv.z, S.z, a4); a4 = fmaf(Bv.w, S.w, a4);
            }
            float f3 = tanhf(a3);
            float f4 = tanhf(a4);
            e4_own = expf(f4);
            float s1e = p1_own * e4_own;
            float t1  = s1e + f3;
            float2* c23 = ((float2*)&cfs[w][l]) + 1;
            *c23 = make_float2(1.f - f3 * f3, s1e * (1.f - f4 * f4));
            out_vec[b * DV + l]       = t1;
            out_vec[b * DV + HBV + l] = s2_own;
        }
        __syncwarp();

        float* jt = out_jt + b * (DV * DV);

        // ---- Fused loop over k: J21 row k (regs), bottom rows, JJ12 row k,
        //      top-right row k. One float4 coef broadcast per k. ----
        float J21r[HBV];
        if (l < HBV) {
            #pragma unroll
            for (int k = 0; k < HBV; k++) {
                float4 c = cfs[w][k];                       // broadcast: 1 wf
                float v21 = fmaf(c.x, W1c[k], c.y * W2c[k]); // pure regs
                J21r[k] = v21;
                jt[(HBV + k) * DV + l]       = v21;
                jt[(HBV + k) * DV + HBV + l] = (l == k) ? e2_own : 0.f;

                float vjj = fmaf(c.z, sw3[k * WPAD + l], c.w * sw4[k * WPAD + l]);
                jjb[w][k * HBV + l]    = vjj;               // for TL matmul
                jt[k * DV + HBV + l]   = vjj * e2_own;      // TR = JJ12*diag(e2)
            }
        }
        __syncwarp();

        // ---- Top-left: diag(e4) + JJ12 @ J21 (float4 broadcast matmul) ----
        if (l < HBV) {
            #pragma unroll 4
            for (int i = 0; i < HBV; i++) {
                const float4* rv = (const float4*)(jjb[w] + i * HBV);
                float m = 0.f;
                #pragma unroll
                for (int g = 0; g < 5; g++) {
                    float4 c = rv[g];
                    m = fmaf(c.x, J21r[4 * g + 0], m);
                    m = fmaf(c.y, J21r[4 * g + 1], m);
                    m = fmaf(c.z, J21r[4 * g + 2], m);
                    m = fmaf(c.w, J21r[4 * g + 3], m);
                }
                if (i == l) m += e4_own;
                jt[i * DV + l] = m;
            }
        }
        __syncwarp();   // protect p1s/s2s/cfs/jjb reuse next iteration
    }
}

extern "C" void kernel_launch(void* const* d_in, const int* in_sizes, int n_in,
                              void* d_out, int out_size) {
    const float* x  = (const float*)d_in[0];
    const float* w1 = (const float*)d_in[1];
    const float* w2 = (const float*)d_in[2];
    const float* w3 = (const float*)d_in[3];
    const float* w4 = (const float*)d_in[4];

    const int B = in_sizes[0] / DV;            // 65536
    float* out_vec = (float*)d_out;            // tuple element 0: (B,1,40)
    float* out_jt  = out_vec + (size_t)B * DV; // tuple element 1: (B,40,40)

    const int blocks = B / (WARPS * EPW);      // 4096
    ende_kernel<<<blocks, 128>>>(x, w1, w2, w3, w4, out_vec, out_jt);
}